// round 3
// baseline (speedup 1.0000x reference)
#include <cuda_runtime.h>

#define NPTS 16384
#define MPTS 4096
#define KNN  16

// ---------------- scratch (device globals; no allocation) ----------------
__device__ float  g_x1[NPTS * 32];
__device__ float4 g_pw[NPTS];       // x, y, z, |p|^2 (fma-chain)
__device__ int    g_idx[MPTS];
__device__ float4 g_np[MPTS];       // sampled coords + |.|^2
__device__ int    g_knn[MPTS * KNN];
__device__ float  g_x2[MPTS * 64];
__device__ float  g_f2[MPTS * 32];

// XLA-matching primitives: ascending-index fma chains
__device__ __forceinline__ float sq3_fma(float x, float y, float z) {
    // fma(z,z, fma(y,y, x*x))  == fused square+reduce, ascending
    return __fmaf_rn(z, z, __fmaf_rn(y, y, __fmul_rn(x, x)));
}
__device__ __forceinline__ float dot3_fma(float ax, float ay, float az,
                                          float bx, float by, float bz) {
    return __fmaf_rn(az, bz, __fmaf_rn(ay, by, __fmul_rn(ax, bx)));
}
// d = (|a|^2 - 2*dot) + |b|^2, left-associated (2*dot is exact)
__device__ __forceinline__ float sqdist_expand(float aw, float dot, float bw) {
    return __fadd_rn(__fsub_rn(aw, __fmul_rn(2.0f, dot)), bw);
}

// ---------------- kernel 1: x1 = relu(bn0(x@w0)); f1 = relu(bn1(x1@w1+b1)) ----------------
__global__ void __launch_bounds__(256) k_pre(
    const float* __restrict__ p, const float* __restrict__ x,
    const float* __restrict__ w0,
    const float* __restrict__ g0, const float* __restrict__ b0,
    const float* __restrict__ m0, const float* __restrict__ v0,
    const float* __restrict__ w1, const float* __restrict__ bias1,
    const float* __restrict__ g1, const float* __restrict__ b1_,
    const float* __restrict__ m1, const float* __restrict__ v1,
    float* __restrict__ out)
{
    __shared__ float x1s[8][32];
    int ch = threadIdx.x & 31;
    int lp = threadIdx.x >> 5;
    int pt = blockIdx.x * 8 + lp;

    float acc = 0.f;
#pragma unroll
    for (int i = 0; i < 6; i++)
        acc = fmaf(__ldg(&x[pt * 6 + i]), __ldg(&w0[i * 32 + ch]), acc);
    float s0 = __ldg(&g0[ch]) / sqrtf(__ldg(&v0[ch]) + 1e-5f);
    float val = (acc - __ldg(&m0[ch])) * s0 + __ldg(&b0[ch]);
    val = fmaxf(val, 0.f);
    x1s[lp][ch] = val;
    g_x1[pt * 32 + ch] = val;

    if (ch == 0) {
        float px = p[pt * 3], py = p[pt * 3 + 1], pz = p[pt * 3 + 2];
        g_pw[pt] = make_float4(px, py, pz, sq3_fma(px, py, pz));
    }
    __syncthreads();

    float a1 = __ldg(&bias1[ch]);
#pragma unroll
    for (int i = 0; i < 32; i++)
        a1 = fmaf(x1s[lp][i], __ldg(&w1[i * 32 + ch]), a1);
    float s1 = __ldg(&g1[ch]) / sqrtf(__ldg(&v1[ch]) + 1e-5f);
    float f1 = (a1 - __ldg(&m1[ch])) * s1 + __ldg(&b1_[ch]);
    out[pt * 32 + ch] = fmaxf(f1, 0.f);
}

// ---------------- kernel 2: farthest point sampling (single persistent block) ----------------
__global__ void __launch_bounds__(1024) k_fps(const float* __restrict__ p)
{
    const int tid = threadIdx.x;
    const int base = tid * 16;

    float dmin[16];
#pragma unroll
    for (int k = 0; k < 16; k++) dmin[k] = 1e10f;

    __shared__ float sv[32];
    __shared__ int   si[32];
    __shared__ int   swin;

    if (tid == 0) g_idx[0] = 0;

    float qx = p[0], qy = p[1], qz = p[2];
    const float4* p4 = reinterpret_cast<const float4*>(p) + tid * 12;

    for (int it = 1; it < MPTS; ++it) {
        float best = -1.f; int bidx = 0;
#pragma unroll
        for (int g = 0; g < 4; g++) {
            float4 A = __ldg(p4 + 3 * g + 0);
            float4 B = __ldg(p4 + 3 * g + 1);
            float4 C = __ldg(p4 + 3 * g + 2);
            float xs[4] = {A.x, A.w, B.z, C.y};
            float ys[4] = {A.y, B.x, B.w, C.z};
            float zs[4] = {A.z, B.y, C.x, C.w};
#pragma unroll
            for (int t = 0; t < 4; t++) {
                int k = 4 * g + t;
                // fma chain, ascending: fma(dz,dz, fma(dy,dy, dx*dx))
                float dx = __fsub_rn(xs[t], qx);
                float dy = __fsub_rn(ys[t], qy);
                float dz = __fsub_rn(zs[t], qz);
                float d = sq3_fma(dx, dy, dz);
                float dm = fminf(dmin[k], d);
                dmin[k] = dm;
                if (dm > best) { best = dm; bidx = base + k; }  // first-max semantics
            }
        }
#pragma unroll
        for (int off = 16; off; off >>= 1) {
            float ov = __shfl_down_sync(0xffffffffu, best, off);
            int   oi = __shfl_down_sync(0xffffffffu, bidx, off);
            if (ov > best || (ov == best && oi < bidx)) { best = ov; bidx = oi; }
        }
        int wid = tid >> 5;
        if ((tid & 31) == 0) { sv[wid] = best; si[wid] = bidx; }
        __syncthreads();
        if (wid == 0) {
            best = sv[tid]; bidx = si[tid];
#pragma unroll
            for (int off = 16; off; off >>= 1) {
                float ov = __shfl_down_sync(0xffffffffu, best, off);
                int   oi = __shfl_down_sync(0xffffffffu, bidx, off);
                if (ov > best || (ov == best && oi < bidx)) { best = ov; bidx = oi; }
            }
            if (tid == 0) { swin = bidx; g_idx[it] = bidx; }
        }
        __syncthreads();
        int w = swin;
        qx = __ldg(&p[3 * w]); qy = __ldg(&p[3 * w + 1]); qz = __ldg(&p[3 * w + 2]);
    }
    __syncthreads();
    for (int i = tid; i < MPTS; i += 1024) {
        int id = g_idx[i];
        g_np[i] = g_pw[id];
    }
}

// ---------------- kernel 3a: top-16 KNN for each sampled point over all N ----------------
__global__ void __launch_bounds__(256) k_knn()
{
    __shared__ float sd[256 * 17];
    __shared__ int   sii[256 * 17];
    int lane = threadIdx.x & 31;
    int part = threadIdx.x >> 5;
    int q = blockIdx.x * 32 + lane;
    float4 nq = __ldg(&g_np[q]);

    float bd[16]; int bi[16];
#pragma unroll
    for (int k = 0; k < 16; k++) { bd[k] = 3.4e38f; bi[k] = 0x7fffffff; }
    float wmax = 3.4e38f; int wpos = 0, widx = 0x7fffffff;

    int j0 = part * 2048;
    for (int j = j0; j < j0 + 2048; ++j) {
        float4 c = __ldg(&g_pw[j]);
        float dot = dot3_fma(nq.x, nq.y, nq.z, c.x, c.y, c.z);
        float d = sqdist_expand(nq.w, dot, c.w);
        if (d < wmax || (d == wmax && j < widx)) {
            bd[wpos] = d; bi[wpos] = j;
            wmax = -1.f; widx = -1;
#pragma unroll
            for (int k = 0; k < 16; k++)
                if (bd[k] > wmax || (bd[k] == wmax && bi[k] > widx)) {
                    wmax = bd[k]; widx = bi[k]; wpos = k;
                }
        }
    }
    int sb = threadIdx.x * 17;
#pragma unroll
    for (int k = 0; k < 16; k++) { sd[sb + k] = bd[k]; sii[sb + k] = bi[k]; }
    __syncthreads();

    if (part == 0) {
#pragma unroll 1
        for (int s = 0; s < 16; s++) {
            float md = 3.5e38f; int mi = 0x7fffffff; int mloc = 0;
            for (int src = 0; src < 8; src++) {
                int tb = (src * 32 + lane) * 17;
#pragma unroll
                for (int e = 0; e < 16; e++) {
                    float dd = sd[tb + e]; int ii = sii[tb + e];
                    if (dd < md || (dd == md && ii < mi)) { md = dd; mi = ii; mloc = tb + e; }
                }
            }
            g_knn[q * 16 + s] = mi;
            sd[mloc] = 3.6e38f;
        }
    }
}

// ---------------- kernel 3b: grouped conv + maxpool over K ----------------
__global__ void __launch_bounds__(64) k_group(
    const float* __restrict__ p, const float* __restrict__ wd,
    const float* __restrict__ gd, const float* __restrict__ bd_,
    const float* __restrict__ md, const float* __restrict__ vd)
{
    __shared__ float fs[16 * 35];
    int q = blockIdx.x;
    int c = threadIdx.x;
    float4 nq = __ldg(&g_np[q]);

    for (int e = c; e < 16 * 35; e += 64) {
        int k = e / 35, i = e - 35 * k;
        int j = __ldg(&g_knn[q * 16 + k]);
        float v;
        if (i < 3) {
            float qq = (i == 0) ? nq.x : (i == 1) ? nq.y : nq.z;
            v = __ldg(&p[j * 3 + i]) - qq;
        } else {
            v = g_x1[j * 32 + (i - 3)];
        }
        fs[e] = v;
    }
    __syncthreads();

    float s  = __ldg(&gd[c]) / sqrtf(__ldg(&vd[c]) + 1e-5f);
    float mm = __ldg(&md[c]);
    float bb = __ldg(&bd_[c]);
    float mx = -3.4e38f;
#pragma unroll 1
    for (int k = 0; k < 16; k++) {
        float acc = 0.f;
#pragma unroll
        for (int i = 0; i < 35; i++)
            acc = fmaf(fs[k * 35 + i], __ldg(&wd[i * 64 + c]), acc);
        float h = fmaxf((acc - mm) * s + bb, 0.f);
        mx = fmaxf(mx, h);
    }
    g_x2[q * 64 + c] = mx;
}

// ---------------- kernel 4: f2 = relu(bn2(x2@w2 + b2)) ----------------
__global__ void __launch_bounds__(256) k_f2(
    const float* __restrict__ w2, const float* __restrict__ b2,
    const float* __restrict__ g2, const float* __restrict__ bb2,
    const float* __restrict__ m2, const float* __restrict__ v2)
{
    int t = blockIdx.x * blockDim.x + threadIdx.x;
    int m = t >> 5, c = t & 31;
    float acc = __ldg(&b2[c]);
#pragma unroll 8
    for (int i = 0; i < 64; i++)
        acc = fmaf(g_x2[m * 64 + i], __ldg(&w2[i * 32 + c]), acc);
    float s = __ldg(&g2[c]) / sqrtf(__ldg(&v2[c]) + 1e-5f);
    float f = (acc - __ldg(&m2[c])) * s + __ldg(&bb2[c]);
    g_f2[t] = fmaxf(f, 0.f);
}

// ---------------- kernel 5: 3-NN inverse-distance interpolation; out = f1 + interp ----------------
__global__ void __launch_bounds__(128) k_interp(float* __restrict__ out)
{
    int pt = blockIdx.x * 128 + threadIdx.x;
    float4 qp = g_pw[pt];

    float d0 = 3.4e38f, d1 = 3.4e38f, d2 = 3.4e38f;
    int   i0 = 0x7ffffffe, i1 = 0x7ffffffe, i2 = 0x7ffffffe;
    for (int j = 0; j < MPTS; ++j) {
        float4 c = __ldg(&g_np[j]);
        float dot = dot3_fma(qp.x, qp.y, qp.z, c.x, c.y, c.z);
        float d = sqdist_expand(qp.w, dot, c.w);
        if (d < d2 || (d == d2 && j < i2)) {
            if (d < d1 || (d == d1 && j < i1)) {
                d2 = d1; i2 = i1;
                if (d < d0 || (d == d0 && j < i0)) { d1 = d0; i1 = i0; d0 = d; i0 = j; }
                else { d1 = d; i1 = j; }
            } else { d2 = d; i2 = j; }
        }
    }
    float w0 = 1.f / (sqrtf(fmaxf(d0, 0.f)) + 1e-8f);
    float w1 = 1.f / (sqrtf(fmaxf(d1, 0.f)) + 1e-8f);
    float w2 = 1.f / (sqrtf(fmaxf(d2, 0.f)) + 1e-8f);
    float ws = w0 + w1 + w2;
    w0 /= ws; w1 /= ws; w2 /= ws;

#pragma unroll
    for (int c = 0; c < 32; c++) {
        float v = g_f2[i0 * 32 + c] * w0 + g_f2[i1 * 32 + c] * w1 + g_f2[i2 * 32 + c] * w2;
        out[pt * 32 + c] += v;
    }
}

// ---------------- launch ----------------
extern "C" void kernel_launch(void* const* d_in, const int* in_sizes, int n_in,
                              void* d_out, int out_size)
{
    const float* p    = (const float*)d_in[0];
    const float* x    = (const float*)d_in[1];
    const float* w0   = (const float*)d_in[2];
    const float* bn0g = (const float*)d_in[3];
    const float* bn0b = (const float*)d_in[4];
    const float* bn0m = (const float*)d_in[5];
    const float* bn0v = (const float*)d_in[6];
    const float* wd   = (const float*)d_in[7];
    const float* bndg = (const float*)d_in[8];
    const float* bndb = (const float*)d_in[9];
    const float* bndm = (const float*)d_in[10];
    const float* bndv = (const float*)d_in[11];
    const float* w1   = (const float*)d_in[12];
    const float* b1   = (const float*)d_in[13];
    const float* bn1g = (const float*)d_in[14];
    const float* bn1b = (const float*)d_in[15];
    const float* bn1m = (const float*)d_in[16];
    const float* bn1v = (const float*)d_in[17];
    const float* w2   = (const float*)d_in[18];
    const float* b2   = (const float*)d_in[19];
    const float* bn2g = (const float*)d_in[20];
    const float* bn2b = (const float*)d_in[21];
    const float* bn2m = (const float*)d_in[22];
    const float* bn2v = (const float*)d_in[23];
    float* out = (float*)d_out;

    k_pre<<<NPTS / 8, 256>>>(p, x, w0, bn0g, bn0b, bn0m, bn0v,
                             w1, b1, bn1g, bn1b, bn1m, bn1v, out);
    k_fps<<<1, 1024>>>(p);
    k_knn<<<MPTS / 32, 256>>>();
    k_group<<<MPTS, 64>>>(p, wd, bndg, bndb, bndm, bndv);
    k_f2<<<MPTS * 32 / 256, 256>>>(w2, b2, bn2g, bn2b, bn2m, bn2v);
    k_interp<<<NPTS / 128, 128>>>(out);
}